// round 14
// baseline (speedup 1.0000x reference)
#include <cuda_runtime.h>
#include <cuda_fp16.h>
#include <cstdint>

#define V      12288
#define E      128
#define NTJ    384                 // N tiles (32 cols each)
#define NTILES (96 * NTJ)          // 36864
#define GRID   456                 // 3 CTAs / SM
#define SSTR   136                 // f16 tile row stride (128 + 8 pad)
#define XSTR   40                  // X smem row stride in floats (32 + 8 pad)
#define A_BYTES (128 * SSTR * 2)                 // 34816
#define B_BYTES (32 * SSTR * 2)                  // 8704
#define X_BYTES (128 * XSTR * 4)                 // 20480
#define SMEM_BYTES (A_BYTES + 2 * B_BYTES + X_BYTES)   // 72704

// ---------------------------------------------------------------------------
__device__ __half g_ctx[V * E];
__device__ __half g_tgt[V * E];

__global__ void convert_kernel(const float* __restrict__ tgt,
                               const float* __restrict__ ctx,
                               float* __restrict__ out) {
    if (blockIdx.x == 0 && threadIdx.x == 0) out[0] = 0.0f;
    int t = blockIdx.x * blockDim.x + threadIdx.x;
    int base = t * 8;
    if (base >= V * E) return;
    float4 a0 = *(const float4*)(tgt + base);
    float4 a1 = *(const float4*)(tgt + base + 4);
    float4 b0 = *(const float4*)(ctx + base);
    float4 b1 = *(const float4*)(ctx + base + 4);
    __half2 ta[4], ca[4];
    ta[0] = __floats2half2_rn(a0.x, a0.y); ta[1] = __floats2half2_rn(a0.z, a0.w);
    ta[2] = __floats2half2_rn(a1.x, a1.y); ta[3] = __floats2half2_rn(a1.z, a1.w);
    ca[0] = __floats2half2_rn(b0.x, b0.y); ca[1] = __floats2half2_rn(b0.z, b0.w);
    ca[2] = __floats2half2_rn(b1.x, b1.y); ca[3] = __floats2half2_rn(b1.z, b1.w);
    *(uint4*)(g_tgt + base) = *(const uint4*)ta;
    *(uint4*)(g_ctx + base) = *(const uint4*)ca;
}

// ---------------------------------------------------------------------------
__device__ __forceinline__ uint32_t smem_u32(const void* p) {
    uint32_t a;
    asm("{ .reg .u64 t; cvta.to.shared.u64 t, %1; cvt.u32.u64 %0, t; }" : "=r"(a) : "l"(p));
    return a;
}
__device__ __forceinline__ void mma_f16(uint32_t c[2], const uint32_t a[4],
                                        const uint32_t b0, const uint32_t b1) {
    asm volatile(
        "mma.sync.aligned.m16n8k16.row.col.f16.f16.f16.f16 "
        "{%0,%1}, {%2,%3,%4,%5}, {%6,%7}, {%0,%1};\n"
        : "+r"(c[0]), "+r"(c[1])
        : "r"(a[0]), "r"(a[1]), "r"(a[2]), "r"(a[3]), "r"(b0), "r"(b1));
}
__device__ __forceinline__ void ldsm_x4(uint32_t r[4], uint32_t addr) {
    asm volatile("ldmatrix.sync.aligned.m8n8.x4.shared.b16 {%0,%1,%2,%3}, [%4];"
                 : "=r"(r[0]), "=r"(r[1]), "=r"(r[2]), "=r"(r[3]) : "r"(addr));
}
__device__ __forceinline__ float lg2f(float v) {
    float r; asm("lg2.approx.f32 %0, %1;" : "=f"(r) : "f"(v)); return r;
}
__device__ __forceinline__ float ex2f(float v) {
    float r; asm("ex2.approx.f32 %0, %1;" : "=f"(r) : "f"(v)); return r;
}
__device__ __forceinline__ float2 lds64(uint32_t addr) {
    float2 v;
    asm volatile("ld.shared.v2.f32 {%0,%1}, [%2];" : "=f"(v.x), "=f"(v.y) : "r"(addr));
    return v;
}
// ---- packed f32x2 helpers ----------------------------------------------------
__device__ __forceinline__ uint64_t pk2(float lo, float hi) {
    uint64_t r; asm("mov.b64 %0, {%1, %2};" : "=l"(r) : "f"(lo), "f"(hi)); return r;
}
__device__ __forceinline__ void upk2(float& lo, float& hi, uint64_t p) {
    asm("mov.b64 {%0, %1}, %2;" : "=f"(lo), "=f"(hi) : "l"(p));
}
__device__ __forceinline__ uint64_t add2(uint64_t a, uint64_t b) {
    uint64_t r; asm("add.rn.f32x2 %0, %1, %2;" : "=l"(r) : "l"(a), "l"(b)); return r;
}
__device__ __forceinline__ uint64_t mul2(uint64_t a, uint64_t b) {
    uint64_t r; asm("mul.rn.f32x2 %0, %1, %2;" : "=l"(r) : "l"(a), "l"(b)); return r;
}
__device__ __forceinline__ uint64_t fma2(uint64_t a, uint64_t b, uint64_t c) {
    uint64_t r; asm("fma.rn.f32x2 %0, %1, %2, %3;" : "=l"(r) : "l"(a), "l"(b), "l"(c)); return r;
}
#define CP_COMMIT() asm volatile("cp.async.commit_group;" ::: "memory")
#define CP_WAIT0()  asm volatile("cp.async.wait_group 0;" ::: "memory")
#define CP_WAIT1()  asm volatile("cp.async.wait_group 1;" ::: "memory")
#define CP_ASYNC16(dst, src) \
    asm volatile("cp.async.cg.shared.global [%0], [%1], 16;" \
                 :: "r"(dst), "l"(src) : "memory")

// Math for 2 elements: scalar feeds MUFU, packed after. No clamp (x<=50).
__device__ __forceinline__ void epi2s(const float2 xv, const uint64_t base,
                                      const uint64_t NLN2, const float CM,
                                      uint64_t& ls) {
    float l10 = lg2f(xv.x + 1.0f);
    float l11 = lg2f(xv.y + 1.0f);
    float w0  = ex2f(fmaf(lg2f(xv.x), 0.75f, CM));
    float w1  = ex2f(fmaf(lg2f(xv.y), 0.75f, CM));
    uint64_t d  = fma2(NLN2, pk2(l10, l11), base);
    uint64_t wd = mul2(pk2(w0, w1), d);
    ls = fma2(wd, d, ls);
}

// ---------------------------------------------------------------------------
// Persistent kernel: 456 CTAs x 256 threads (3 CTA/SM). Tile 128(M) x 32(N).
// X via cp.async into smem (GEMM hides latency). Band loop — no divisions,
// incremental pointers, cb hoisted to registers per band.
// ---------------------------------------------------------------------------
__global__ void __launch_bounds__(256, 3)
glove_il(const float* __restrict__ X,
         const float* __restrict__ tb,
         const float* __restrict__ cb,
         float* __restrict__ out) {
    extern __shared__ char smem[];
    __half* As  = (__half*)smem;
    const uint32_t bs0_u32 = smem_u32(smem + A_BYTES);
    const uint32_t xs_u32  = smem_u32(smem + A_BYTES + 2 * B_BYTES);
    __shared__ float red[8];

    const int tid  = threadIdx.x;
    const int warp = tid >> 5;
    const int lane = tid & 31;
    const int wm   = warp >> 1;          // 0..3 -> 32-row band
    const int wn   = warp & 1;           // 0..1 -> 16-col band
    const int g    = lane >> 2;
    const int tig  = lane & 3;
    const int m0   = wm * 32;
    const int n0   = wn * 16;
    const int colb = n0 + 2 * tig;

    const int arow = (lane & 15);
    const int acol = (lane >> 4) << 3;
    const uint32_t aAddr0 = smem_u32(As + (m0 + arow) * SSTR + acol);
    const uint32_t aAddr1 = aAddr0 + 16 * SSTR * 2;
    const int bstrip = (lane >> 4);
    const int bkh    = ((lane >> 3) & 1) << 3;
    const int brow   = (lane & 7);
    const uint32_t bOff = (uint32_t)(((n0 + bstrip * 8 + brow) * SSTR + bkh) * 2);

    // Loop-invariant epilogue Xs addresses (4 row-groups x col base).
    uint32_t xaddr[4];
    #pragma unroll
    for (int k = 0; k < 4; k++) {
        const int row = m0 + 16 * (k >> 1) + 8 * (k & 1) + g;
        xaddr[k] = xs_u32 + (uint32_t)((row * XSTR + colb) * 4);
    }
    // Loop-invariant per-thread staging offsets.
    const int xrow_off = tid >> 3;               // X stage: rows tid>>3 + 32*k2
    const int xpart    = (tid & 7) * 4;
    const uint32_t xdst0 = xs_u32 + (uint32_t)(xrow_off * (XSTR * 4) + xpart * 4);
    const int brow_off = tid >> 4;               // B stage: rows tid>>4 + 16*k2
    const int bpart    = (tid & 15) * 8;
    const uint32_t bdst0 = (uint32_t)(brow_off * (SSTR * 2) + bpart * 2);

    const uint64_t NLN2 = pk2(-0.69314718f, -0.69314718f);
    const float    CM   = -4.98289214f;

    const int per = NTILES / GRID, rem = NTILES % GRID;
    const int bidx = blockIdx.x;
    const int start = bidx * per + (bidx < rem ? bidx : rem);
    const int cnt = per + (bidx < rem ? 1 : 0);

    int bi = start / NTJ;                 // the only division
    int bj = start - bi * NTJ;

    // ---- prologue: stage A(bi), B(bj) plain; load cb regs ----------------------
    uint64_t cbp[4];
    {
        const __half* gA = g_ctx + (size_t)(bi * 128) * E;
        const __half* gB = g_tgt + (size_t)(bj * 32) * E;
        #pragma unroll
        for (int u = tid; u < 128 * 16; u += 256) {
            int row = u >> 4, part = u & 15;
            *(uint4*)(As + row * SSTR + part * 8) = *(const uint4*)(gA + row * E + part * 8);
        }
        #pragma unroll
        for (int u = tid; u < 32 * 16; u += 256) {
            int row = u >> 4, part = u & 15;
            *(uint4*)((char*)smem + A_BYTES + row * (SSTR * 2) + part * 16) =
                *(const uint4*)(gB + row * E + part * 8);
        }
        #pragma unroll
        for (int k = 0; k < 4; k++) {
            float c = __ldg(cb + bi * 128 + m0 + 16 * (k >> 1) + 8 * (k & 1) + g);
            cbp[k] = pk2(c, c);
        }
    }
    __syncthreads();

    // Incremental pointers.
    const float* xsrc = X + (size_t)(bi * 128 + xrow_off) * V + bj * 32 + xpart;
    const float* tbptr = tb + bj * 32 + colb;

    uint32_t acc[2][2][2];
    uint64_t ls0 = 0ull, ls1 = 0ull;
    int buf = 0;
    bool newband = false;

    for (int it = 0; it < cnt; ++it) {
        CP_WAIT0();                 // B(t) arrived (no-op first iter)
        __syncthreads();            // B(t) visible; Xs free

        if (newband) {              // rare: restage A + reload cb
            const __half* gA = g_ctx + (size_t)(bi * 128) * E;
            #pragma unroll
            for (int u = tid; u < 128 * 16; u += 256) {
                int row = u >> 4, part = u & 15;
                *(uint4*)(As + row * SSTR + part * 8) =
                    *(const uint4*)(gA + row * E + part * 8);
            }
            #pragma unroll
            for (int k = 0; k < 4; k++) {
                float c = __ldg(cb + bi * 128 + m0 + 16 * (k >> 1) + 8 * (k & 1) + g);
                cbp[k] = pk2(c, c);
            }
            newband = false;
            __syncthreads();
        }

        // ---- issue async X(t) and B(t+1) -----------------------------------
        {
            #pragma unroll
            for (int k2 = 0; k2 < 4; k2++)
                CP_ASYNC16(xdst0 + (uint32_t)(k2 * 32 * XSTR * 4),
                           __cvta_generic_to_global(xsrc + (size_t)(k2 * 32) * V));
            CP_COMMIT();
        }
        if (it + 1 < cnt) {
            int bjn = bj + 1;
            if (bjn == NTJ) bjn = 0;
            const __half* gB = g_tgt + (size_t)(bjn * 32 + brow_off) * E + bpart;
            const uint32_t bdst = bs0_u32 + (uint32_t)((buf ^ 1) * B_BYTES) + bdst0;
            CP_ASYNC16(bdst, __cvta_generic_to_global(gB));
            CP_ASYNC16(bdst + (uint32_t)(16 * SSTR * 2),
                       __cvta_generic_to_global(gB + 16 * E));
            CP_COMMIT();
        }

        // ---- GEMM(t): warp 32x16, K=128 (hides X stream) --------------------
        const uint32_t bA = bs0_u32 + (uint32_t)(buf * B_BYTES) + bOff;
        #pragma unroll
        for (int mt = 0; mt < 2; mt++)
            #pragma unroll
            for (int nt = 0; nt < 2; nt++)
                { acc[mt][nt][0] = 0u; acc[mt][nt][1] = 0u; }
        #pragma unroll
        for (int s = 0; s < 8; s++) {
            const uint32_t koff = s * 32;
            uint32_t afr0[4], afr1[4], bfr[4];
            ldsm_x4(afr0, aAddr0 + koff);
            ldsm_x4(afr1, aAddr1 + koff);
            ldsm_x4(bfr,  bA + koff);
            mma_f16(acc[0][0], afr0, bfr[0], bfr[1]);
            mma_f16(acc[0][1], afr0, bfr[2], bfr[3]);
            mma_f16(acc[1][0], afr1, bfr[0], bfr[1]);
            mma_f16(acc[1][1], afr1, bfr[2], bfr[3]);
        }

        if (it + 1 < cnt) CP_WAIT1();   // X(t) done, B(t+1) may fly
        else              CP_WAIT0();   // last tile: ONLY X in flight
        __syncthreads();

        // ---- epilogue --------------------------------------------------------
        {
            uint64_t tbp0, tbp1;
            {
                float2 t0 = *(const float2*)(tbptr);
                float2 t1 = *(const float2*)(tbptr + 8);
                tbp0 = pk2(t0.x, t0.y);
                tbp1 = pk2(t1.x, t1.y);
            }
            #pragma unroll
            for (int k = 0; k < 4; k++) {
                const int mt = k >> 1, h = k & 1;
                float2 xv0 = lds64(xaddr[k]);
                float2 xv1 = lds64(xaddr[k] + 32);
                float2 a0 = __half22float2(*reinterpret_cast<const __half2*>(&acc[mt][0][h]));
                float2 a1 = __half22float2(*reinterpret_cast<const __half2*>(&acc[mt][1][h]));
                uint64_t base0 = add2(pk2(a0.x, a0.y), add2(tbp0, cbp[k]));
                uint64_t base1 = add2(pk2(a1.x, a1.y), add2(tbp1, cbp[k]));
                epi2s(xv0, base0, NLN2, CM, ls0);
                epi2s(xv1, base1, NLN2, CM, ls1);
            }
        }

        // ---- advance ---------------------------------------------------------
        buf ^= 1;
        bj++;
        if (bj == NTJ) {
            bj = 0; bi++; newband = true;
            xsrc  = X + (size_t)(bi * 128 + xrow_off) * V + xpart;
            tbptr = tb + colb;
        } else {
            xsrc  += 32;
            tbptr += 32;
        }
    }

    // ---- reduce + one atomic per CTA ---------------------------------------------
    float la, lb, lc, ld;
    upk2(la, lb, ls0); upk2(lc, ld, ls1);
    float lsum = (la + lb) + (lc + ld);
    #pragma unroll
    for (int off = 16; off; off >>= 1) lsum += __shfl_xor_sync(0xFFFFFFFFu, lsum, off);
    if (lane == 0) red[warp] = lsum;
    __syncthreads();
    if (tid == 0) {
        float s = 0.0f;
        #pragma unroll
        for (int w = 0; w < 8; ++w) s += red[w];
        atomicAdd(out, s);
    }
}

// ---------------------------------------------------------------------------
extern "C" void kernel_launch(void* const* d_in, const int* in_sizes, int n_in,
                              void* d_out, int out_size) {
    const float* X   = (const float*)d_in[0];
    const float* te  = (const float*)d_in[1];
    const float* ce  = (const float*)d_in[2];
    const float* tbp = (const float*)d_in[3];
    const float* cbp = (const float*)d_in[4];
    float* out = (float*)d_out;

    static bool attr_set = false;
    if (!attr_set) {
        cudaFuncSetAttribute(glove_il, cudaFuncAttributeMaxDynamicSharedMemorySize,
                             SMEM_BYTES);
        attr_set = true;
    }

    const int conv_threads = V * E / 8;
    convert_kernel<<<(conv_threads + 255) / 256, 256>>>(te, ce, out);

    glove_il<<<GRID, 256, SMEM_BYTES>>>(X, tbp, cbp, out);
    (void)in_sizes; (void)n_in; (void)out_size;
}